// round 5
// baseline (speedup 1.0000x reference)
#include <cuda_runtime.h>

// ---------------------------------------------------------------------------
// AttentiveStateMLP fused kernel.
// B=131072 rows, each: 5 encoders -> 5 tokens(64) -> qkv -> 4-head attn(S=5)
// -> out proj -> residual+LN -> mean pool -> 128-dim relu head.
//
// Optimization: qkv[s] = Wqkv @ (P_s @ f_s + pb_s) + bqkv
//             = (Wqkv @ P_s) @ f_s + (Wqkv @ pb_s + bqkv)
// The fused matrices (192 x 144 total) are precomputed each launch by a tiny
// prep kernel into __device__ globals (graph-capturable, no allocs).
// Main kernel: one warp per row, 8 rows / 256-thread block.
// ---------------------------------------------------------------------------

#define BATCH 131072
#define WARPS_PER_BLOCK 8
#define ROW_SMEM 1488   // floats per row: sx/pooled 64 | f 144 | qkv 960 | ctx 320

__device__ float g_WP[192 * 144];  // fused (Wqkv @ P_s), column blocks per segment
__device__ float g_qb[5 * 192];    // fused bias per token: Wqkv @ pb_s + bqkv

// segment column offsets within the 144-wide feature vector, and dims
// phys[0:64] obj[64:96] mine[96:112] prog[112:128] seq[128:144]

__global__ void prep_kernel(
    const float* __restrict__ Wqkv, const float* __restrict__ bqkv,
    const float* __restrict__ P_phys, const float* __restrict__ pb_phys,
    const float* __restrict__ P_obj,  const float* __restrict__ pb_obj,
    const float* __restrict__ P_mine, const float* __restrict__ pb_mine,
    const float* __restrict__ P_prog, const float* __restrict__ pb_prog,
    const float* __restrict__ P_seq,  const float* __restrict__ pb_seq)
{
    int idx = blockIdx.x * blockDim.x + threadIdx.x;
    if (idx < 192 * 144) {
        int j = idx / 144;
        int col = idx - j * 144;
        const float* P; int d, dim;
        if (col < 64)       { P = P_phys; d = col;       dim = 64; }
        else if (col < 96)  { P = P_obj;  d = col - 64;  dim = 32; }
        else if (col < 112) { P = P_mine; d = col - 96;  dim = 16; }
        else if (col < 128) { P = P_prog; d = col - 112; dim = 16; }
        else                { P = P_seq;  d = col - 128; dim = 16; }
        float acc = 0.f;
        #pragma unroll 8
        for (int c = 0; c < 64; c++) acc = fmaf(Wqkv[j * 64 + c], P[c * dim + d], acc);
        g_WP[idx] = acc;
    }
    if (idx < 5 * 192) {
        int s = idx / 192;
        int j = idx - s * 192;
        const float* pb = (s == 0) ? pb_phys : (s == 1) ? pb_obj :
                          (s == 2) ? pb_mine : (s == 3) ? pb_prog : pb_seq;
        float acc = bqkv[j];
        #pragma unroll 8
        for (int c = 0; c < 64; c++) acc = fmaf(Wqkv[j * 64 + c], pb[c], acc);
        g_qb[idx] = acc;
    }
}

__device__ __forceinline__ float dot4(float4 a, float4 b, float acc) {
    acc = fmaf(a.x, b.x, acc);
    acc = fmaf(a.y, b.y, acc);
    acc = fmaf(a.z, b.z, acc);
    acc = fmaf(a.w, b.w, acc);
    return acc;
}

template <int DIM>
__device__ __forceinline__ void token_pair(
    const float* __restrict__ P, const float* __restrict__ pb,
    const float* sfseg, int lane, float& t0, float& t1)
{
    float a0 = pb[lane], a1 = pb[lane + 32];
    const float4* p0 = reinterpret_cast<const float4*>(P + lane * DIM);
    const float4* p1 = reinterpret_cast<const float4*>(P + (lane + 32) * DIM);
    const float4* fv = reinterpret_cast<const float4*>(sfseg);
    #pragma unroll
    for (int k = 0; k < DIM / 4; k++) {
        float4 f = fv[k];
        a0 = dot4(p0[k], f, a0);
        a1 = dot4(p1[k], f, a1);
    }
    t0 = a0; t1 = a1;
}

__global__ __launch_bounds__(WARPS_PER_BLOCK * 32, 2)
void fused_kernel(
    const float* __restrict__ x,
    const float* __restrict__ W_phys, const float* __restrict__ b_phys,
    const float* __restrict__ W_obj,  const float* __restrict__ b_obj,
    const float* __restrict__ W_mine, const float* __restrict__ b_mine,
    const float* __restrict__ W_prog, const float* __restrict__ b_prog,
    const float* __restrict__ W_seq,  const float* __restrict__ b_seq,
    const float* __restrict__ P_phys, const float* __restrict__ pb_phys,
    const float* __restrict__ P_obj,  const float* __restrict__ pb_obj,
    const float* __restrict__ P_mine, const float* __restrict__ pb_mine,
    const float* __restrict__ P_prog, const float* __restrict__ pb_prog,
    const float* __restrict__ P_seq,  const float* __restrict__ pb_seq,
    const float* __restrict__ Wo, const float* __restrict__ bo,
    const float* __restrict__ gamma, const float* __restrict__ beta,
    const float* __restrict__ Wp, const float* __restrict__ bp,
    float* __restrict__ out)
{
    __shared__ float smem[WARPS_PER_BLOCK][ROW_SMEM];
    const int warp = threadIdx.x >> 5;
    const int lane = threadIdx.x & 31;
    const int row  = blockIdx.x * WARPS_PER_BLOCK + warp;

    float* S     = smem[warp];
    float* sx    = S;            // 64 floats: x (58 used); later reused for pooled
    float* sf    = S + 64;       // 144 floats: relu features
    float* sqkv  = S + 208;      // 960 floats: qkv per token (5 x 192)
    float* sctx  = S + 1168;     // 320 floats: attention context (5 x 64)

    // ---- load x row into smem ----
    const float* xr = x + (size_t)row * 58;
    sx[lane] = xr[lane];
    if (lane < 26) sx[lane + 32] = xr[lane + 32];
    __syncwarp();

    // ---- feature encoders (relu MLPs) ----
    {   // phys: 64 outputs, dot over x[0:29]
        float a0 = b_phys[lane], a1 = b_phys[lane + 32];
        const float* w0 = W_phys + lane * 29;
        const float* w1 = W_phys + (lane + 32) * 29;
        #pragma unroll
        for (int k = 0; k < 29; k++) {
            float xv = sx[k];
            a0 = fmaf(w0[k], xv, a0);
            a1 = fmaf(w1[k], xv, a1);
        }
        sf[lane] = fmaxf(a0, 0.f);
        sf[lane + 32] = fmaxf(a1, 0.f);
    }
    {   // obj: 32 outputs, dot over x[29:44]
        float a = b_obj[lane];
        const float* w = W_obj + lane * 15;
        #pragma unroll
        for (int k = 0; k < 15; k++) a = fmaf(w[k], sx[29 + k], a);
        sf[64 + lane] = fmaxf(a, 0.f);
    }
    if (lane < 16) {
        // mine: 16 outputs, dot x[44:52]
        float a = b_mine[lane];
        const float* w = W_mine + lane * 8;
        #pragma unroll
        for (int k = 0; k < 8; k++) a = fmaf(w[k], sx[44 + k], a);
        sf[96 + lane] = fmaxf(a, 0.f);
        // prog: 16 outputs, dot x[52:55]
        float b = b_prog[lane];
        const float* wq = W_prog + lane * 3;
        #pragma unroll
        for (int k = 0; k < 3; k++) b = fmaf(wq[k], sx[52 + k], b);
        sf[112 + lane] = fmaxf(b, 0.f);
        // seq: 16 outputs, dot x[55:58]
        float c = b_seq[lane];
        const float* ws = W_seq + lane * 3;
        #pragma unroll
        for (int k = 0; k < 3; k++) c = fmaf(ws[k], sx[55 + k], c);
        sf[128 + lane] = fmaxf(c, 0.f);
    }
    __syncwarp();

    // ---- tokens (needed for residual): token[s][c], c = lane, lane+32 ----
    float tok0[5], tok1[5];
    token_pair<64>(P_phys, pb_phys, sf +   0, lane, tok0[0], tok1[0]);
    token_pair<32>(P_obj,  pb_obj,  sf +  64, lane, tok0[1], tok1[1]);
    token_pair<16>(P_mine, pb_mine, sf +  96, lane, tok0[2], tok1[2]);
    token_pair<16>(P_prog, pb_prog, sf + 112, lane, tok0[3], tok1[3]);
    token_pair<16>(P_seq,  pb_seq,  sf + 128, lane, tok0[4], tok1[4]);

    // ---- fused qkv: qkv[s][j] = g_qb[s][j] + WP[j, seg_s] . f_seg_s ----
    {
        const int SEG_OFF[5] = {0, 64, 96, 112, 128};
        const int SEG_DIM[5] = {64, 32, 16, 16, 16};
        #pragma unroll
        for (int s = 0; s < 5; s++) {
            const int off = SEG_OFF[s];
            const int dim = SEG_DIM[s];
            const float4* fv = reinterpret_cast<const float4*>(sf + off);
            float acc[6];
            #pragma unroll
            for (int m = 0; m < 6; m++) acc[m] = g_qb[s * 192 + lane + 32 * m];
            #pragma unroll
            for (int k = 0; k < dim / 4; k++) {
                float4 f = fv[k];
                #pragma unroll
                for (int m = 0; m < 6; m++) {
                    const float4 w = *reinterpret_cast<const float4*>(
                        g_WP + (lane + 32 * m) * 144 + off + 4 * k);
                    acc[m] = dot4(w, f, acc[m]);
                }
            }
            #pragma unroll
            for (int m = 0; m < 6; m++) sqkv[s * 192 + lane + 32 * m] = acc[m];
        }
    }
    __syncwarp();

    // ---- attention: lanes 0..19, unit (head h, query token i) ----
    if (lane < 20) {
        const int h = lane / 5;
        const int i = lane - h * 5;
        const float* q = sqkv + i * 192 + h * 16;
        float sc[5];
        #pragma unroll
        for (int j = 0; j < 5; j++) {
            const float* kk = sqkv + j * 192 + 64 + h * 16;
            float d = 0.f;
            #pragma unroll
            for (int t = 0; t < 16; t++) d = fmaf(q[t], kk[t], d);
            sc[j] = d * 0.25f;   // / sqrt(HD=16)
        }
        float mx = sc[0];
        #pragma unroll
        for (int j = 1; j < 5; j++) mx = fmaxf(mx, sc[j]);
        float sum = 0.f;
        #pragma unroll
        for (int j = 0; j < 5; j++) { sc[j] = __expf(sc[j] - mx); sum += sc[j]; }
        const float inv = 1.f / sum;
        #pragma unroll
        for (int t = 0; t < 16; t++) {
            float c = 0.f;
            #pragma unroll
            for (int j = 0; j < 5; j++)
                c = fmaf(sc[j], sqkv[j * 192 + 128 + h * 16 + t], c);
            sctx[i * 64 + h * 16 + t] = c * inv;
        }
    }
    __syncwarp();

    // ---- out proj + residual + LayerNorm + pool ----
    float p0 = 0.f, p1 = 0.f;
    const float g0 = gamma[lane], g1 = gamma[lane + 32];
    const float be0 = beta[lane], be1 = beta[lane + 32];
    const float bo0 = bo[lane],   bo1 = bo[lane + 32];
    const float4* w0 = reinterpret_cast<const float4*>(Wo + lane * 64);
    const float4* w1 = reinterpret_cast<const float4*>(Wo + (lane + 32) * 64);
    #pragma unroll
    for (int s = 0; s < 5; s++) {
        float a0 = bo0, a1 = bo1;
        const float4* cv = reinterpret_cast<const float4*>(sctx + s * 64);
        #pragma unroll
        for (int k = 0; k < 16; k++) {
            float4 c = cv[k];
            a0 = dot4(w0[k], c, a0);
            a1 = dot4(w1[k], c, a1);
        }
        float h0 = tok0[s] + a0;
        float h1 = tok1[s] + a1;
        // mean over 64 = warp-sum of (h0 + h1) / 64
        float sum = h0 + h1;
        #pragma unroll
        for (int o = 16; o > 0; o >>= 1) sum += __shfl_xor_sync(0xffffffff, sum, o);
        const float mu = sum * (1.f / 64.f);
        const float d0 = h0 - mu, d1 = h1 - mu;
        float v = d0 * d0 + d1 * d1;
        #pragma unroll
        for (int o = 16; o > 0; o >>= 1) v += __shfl_xor_sync(0xffffffff, v, o);
        const float invstd = rsqrtf(v * (1.f / 64.f) + 1e-5f);
        p0 = fmaf(d0 * invstd, g0, p0 + be0);
        p1 = fmaf(d1 * invstd, g1, p1 + be1);
    }
    p0 *= 0.2f;
    p1 *= 0.2f;
    __syncwarp();
    sx[lane] = p0;           // reuse x region for pooled vector
    sx[lane + 32] = p1;
    __syncwarp();

    // ---- head: out[o] = relu(Wp[o] . pooled + bp[o]), o = lane + 32m ----
    const float4* pv = reinterpret_cast<const float4*>(sx);
    float* orow = out + (size_t)row * 128;
    #pragma unroll
    for (int m = 0; m < 4; m++) {
        const int o = lane + 32 * m;
        float a = bp[o];
        const float4* w = reinterpret_cast<const float4*>(Wp + o * 64);
        #pragma unroll
        for (int k = 0; k < 16; k++) a = dot4(w[k], pv[k], a);
        orow[o] = fmaxf(a, 0.f);
    }
}

extern "C" void kernel_launch(void* const* d_in, const int* in_sizes, int n_in,
                              void* d_out, int out_size)
{
    const float* x       = (const float*)d_in[0];
    const float* W_phys  = (const float*)d_in[1];
    const float* b_phys  = (const float*)d_in[2];
    const float* W_obj   = (const float*)d_in[3];
    const float* b_obj   = (const float*)d_in[4];
    const float* W_mine  = (const float*)d_in[5];
    const float* b_mine  = (const float*)d_in[6];
    const float* W_prog  = (const float*)d_in[7];
    const float* b_prog  = (const float*)d_in[8];
    const float* W_seq   = (const float*)d_in[9];
    const float* b_seq   = (const float*)d_in[10];
    const float* P_phys  = (const float*)d_in[11];
    const float* pb_phys = (const float*)d_in[12];
    const float* P_obj   = (const float*)d_in[13];
    const float* pb_obj  = (const float*)d_in[14];
    const float* P_mine  = (const float*)d_in[15];
    const float* pb_mine = (const float*)d_in[16];
    const float* P_prog  = (const float*)d_in[17];
    const float* pb_prog = (const float*)d_in[18];
    const float* P_seq   = (const float*)d_in[19];
    const float* pb_seq  = (const float*)d_in[20];
    const float* Wqkv    = (const float*)d_in[21];
    const float* bqkv    = (const float*)d_in[22];
    const float* Wo      = (const float*)d_in[23];
    const float* bo      = (const float*)d_in[24];
    const float* gamma   = (const float*)d_in[25];
    const float* beta    = (const float*)d_in[26];
    const float* Wp      = (const float*)d_in[27];
    const float* bp      = (const float*)d_in[28];
    float* out = (float*)d_out;

    prep_kernel<<<108, 256>>>(Wqkv, bqkv, P_phys, pb_phys, P_obj, pb_obj,
                              P_mine, pb_mine, P_prog, pb_prog, P_seq, pb_seq);

    fused_kernel<<<BATCH / WARPS_PER_BLOCK, WARPS_PER_BLOCK * 32>>>(
        x,
        W_phys, b_phys, W_obj, b_obj, W_mine, b_mine,
        W_prog, b_prog, W_seq, b_seq,
        P_phys, pb_phys, P_obj, pb_obj, P_mine, pb_mine,
        P_prog, pb_prog, P_seq, pb_seq,
        Wo, bo, gamma, beta, Wp, bp,
        out);
}

// round 7
// speedup vs baseline: 5.9609x; 5.9609x over previous
#include <cuda_runtime.h>

// ---------------------------------------------------------------------------
// AttentiveStateMLP — persistent block-tiled rewrite.
// R5 ncu: L1 90% / fma 5.5% -> old kernel L1-wavefront bound on uncoalesced
// per-row weight loads. Here: k-major weights, smem-resident combined matrix
// M = [P_s ; Wqkv@P_s] (one GEMM -> tok|q|k|v), 8-row register tiling so
// every weight load feeds 8 FMAs. FFMA-pipe-bound by design.
// ---------------------------------------------------------------------------

#define BATCH   131072
#define RTILE   8
#define NTILES  (BATCH / RTILE)     // 16384
#define GRID    304
#define NTHR    256

// smem layout (floats)
#define OFF_M    0          // 36864 : combined M, k-major [c(144)][j(256)]
#define OFF_ENC  36864      // 2560  : encoder weights, k-major
#define OFF_B    39424      // 336   : biases: enc(144) bo(64) gamma(64) beta(64)
#define OFF_X    39760      // 512   : x tile 8 x 64
#define OFF_F    40272      // 1152  : features 8 x 144
#define OFF_Y    41424      // 10240 : 8 x 5 x 256  (tok|q|k|v per token)
#define OFF_P    51664      // 512   : pooled 8 x 64
#define SMEM_FL  52176
#define SMEM_BYTES (SMEM_FL * 4)    // 208704 bytes

// enc sub-offsets within OFF_ENC
#define E_PHYS 0       // 29 x 64
#define E_OBJ  1856    // 15 x 32
#define E_MINE 2336    // 8 x 16
#define E_PROG 2464    // 3 x 16
#define E_SEQ  2512    // 3 x 16

__device__ float g_M[144 * 256];   // k-major combined matrix
__device__ float g_Mb[5 * 256];    // per-token bias for M outputs
__device__ float g_encT[2560];     // k-major encoder weights
__device__ float g_WoT[64 * 64];   // WoT[c*64+j] = Wo[j][c]
__device__ float g_WpT[64 * 128];  // WpT[c*128+o] = Wp[o][c]

// ---------------------------------------------------------------------------
__global__ void prep_kernel(
    const float* __restrict__ Wqkv, const float* __restrict__ bqkv,
    const float* __restrict__ P_phys, const float* __restrict__ pb_phys,
    const float* __restrict__ P_obj,  const float* __restrict__ pb_obj,
    const float* __restrict__ P_mine, const float* __restrict__ pb_mine,
    const float* __restrict__ P_prog, const float* __restrict__ pb_prog,
    const float* __restrict__ P_seq,  const float* __restrict__ pb_seq,
    const float* __restrict__ W_phys, const float* __restrict__ W_obj,
    const float* __restrict__ W_mine, const float* __restrict__ W_prog,
    const float* __restrict__ W_seq,
    const float* __restrict__ Wo, const float* __restrict__ Wp)
{
    int idx = blockIdx.x * blockDim.x + threadIdx.x;

    if (idx < 36864) {                       // g_M[cg*256 + j]
        int cg = idx >> 8;
        int j  = idx & 255;
        const float* P; int dim, c;
        if (cg < 64)       { P = P_phys; dim = 64; c = cg; }
        else if (cg < 96)  { P = P_obj;  dim = 32; c = cg - 64; }
        else if (cg < 112) { P = P_mine; dim = 16; c = cg - 96; }
        else if (cg < 128) { P = P_prog; dim = 16; c = cg - 112; }
        else               { P = P_seq;  dim = 16; c = cg - 128; }
        float v;
        if (j < 64) {
            v = P[j * dim + c];
        } else {
            int jq = j - 64;
            float a = 0.f;
            for (int k = 0; k < 64; k++)
                a = fmaf(Wqkv[jq * 64 + k], P[k * dim + c], a);
            v = a;
        }
        g_M[idx] = v;
        return;
    }
    int i2 = idx - 36864;                    // g_Mb: 1280
    if (i2 < 1280) {
        int s = i2 >> 8;
        int j = i2 & 255;
        const float* pb = (s == 0) ? pb_phys : (s == 1) ? pb_obj :
                          (s == 2) ? pb_mine : (s == 3) ? pb_prog : pb_seq;
        float v;
        if (j < 64) {
            v = pb[j];
        } else {
            int jq = j - 64;
            float a = bqkv[jq];
            for (int k = 0; k < 64; k++)
                a = fmaf(Wqkv[jq * 64 + k], pb[k], a);
            v = a;
        }
        g_Mb[i2] = v;
        return;
    }
    int i3 = idx - 38144;                    // g_encT: 2560
    if (i3 < 2560) {
        float v;
        if (i3 < E_OBJ)        { int t = i3;          v = W_phys[(t & 63) * 29 + (t >> 6)]; }
        else if (i3 < E_MINE)  { int t = i3 - E_OBJ;  v = W_obj [(t & 31) * 15 + (t >> 5)]; }
        else if (i3 < E_PROG)  { int t = i3 - E_MINE; v = W_mine[(t & 15) *  8 + (t >> 4)]; }
        else if (i3 < E_SEQ)   { int t = i3 - E_PROG; v = W_prog[(t & 15) *  3 + (t >> 4)]; }
        else                   { int t = i3 - E_SEQ;  v = W_seq [(t & 15) *  3 + (t >> 4)]; }
        g_encT[i3] = v;
        return;
    }
    int i4 = idx - 40704;                    // g_WoT: 4096
    if (i4 < 4096) {
        int c = i4 >> 6, j = i4 & 63;
        g_WoT[i4] = Wo[j * 64 + c];
        return;
    }
    int i5 = idx - 44800;                    // g_WpT: 8192
    if (i5 < 8192) {
        int c = i5 >> 7, o = i5 & 127;
        g_WpT[i5] = Wp[o * 64 + c];
    }
}

// ---------------------------------------------------------------------------
template <int SOFF, int SDIM>
__device__ __forceinline__ void mgemm_seg(const float* __restrict__ sM,
                                          const float* __restrict__ sF,
                                          float* acc, int j)
{
    const float* Ms = sM + SOFF * 256 + j;
    #pragma unroll 4
    for (int c = 0; c < SDIM; c += 4) {
        float w0 = Ms[(c + 0) * 256];
        float w1 = Ms[(c + 1) * 256];
        float w2 = Ms[(c + 2) * 256];
        float w3 = Ms[(c + 3) * 256];
        #pragma unroll
        for (int r = 0; r < RTILE; r++) {
            float4 f = *reinterpret_cast<const float4*>(sF + r * 144 + SOFF + c);
            acc[r] = fmaf(f.x, w0, fmaf(f.y, w1, fmaf(f.z, w2, fmaf(f.w, w3, acc[r]))));
        }
    }
}

__global__ __launch_bounds__(NTHR, 1)
void fused_kernel(
    const float* __restrict__ x,
    const float* __restrict__ b_phys, const float* __restrict__ b_obj,
    const float* __restrict__ b_mine, const float* __restrict__ b_prog,
    const float* __restrict__ b_seq,
    const float* __restrict__ bo, const float* __restrict__ gamma,
    const float* __restrict__ beta, const float* __restrict__ bp,
    float* __restrict__ out)
{
    extern __shared__ float sm[];
    float* sM   = sm + OFF_M;
    float* sEnc = sm + OFF_ENC;
    float* sB   = sm + OFF_B;
    float* sX   = sm + OFF_X;
    float* sF   = sm + OFF_F;
    float* sY   = sm + OFF_Y;
    float* sP   = sm + OFF_P;

    const int tid  = threadIdx.x;
    const int w    = tid >> 5;
    const int lane = tid & 31;

    // ---- load all weights into smem once per block ----
    for (int i = tid; i < 36864; i += NTHR) sM[i]   = g_M[i];
    for (int i = tid; i < 2560;  i += NTHR) sEnc[i] = g_encT[i];
    for (int i = tid; i < 336; i += NTHR) {
        float v;
        if (i < 64)       v = b_phys[i];
        else if (i < 96)  v = b_obj[i - 64];
        else if (i < 112) v = b_mine[i - 96];
        else if (i < 128) v = b_prog[i - 112];
        else if (i < 144) v = b_seq[i - 128];
        else if (i < 208) v = bo[i - 144];
        else if (i < 272) v = gamma[i - 208];
        else              v = beta[i - 272];
        sB[i] = v;
    }
    __syncthreads();

    for (int tile = blockIdx.x; tile < NTILES; tile += gridDim.x) {
        const int base = tile * RTILE;

        // ---- phase 0: load x tile (coalesced: idx == linear offset) ----
        for (int i = tid; i < RTILE * 58; i += NTHR) {
            int r = i / 58, c = i - r * 58;
            sX[r * 64 + c] = x[(size_t)base * 58 + i];
        }
        __syncthreads();

        // ---- phase 1: encoders, warp = row ----
        {
            const float* xr = sX + w * 64;
            float* fr = sF + w * 144;
            // phys: 64 outputs over x[0:29]
            float a0 = sB[lane], a1 = sB[lane + 32];
            #pragma unroll
            for (int c = 0; c < 29; c++) {
                float xv = xr[c];
                a0 = fmaf(sEnc[E_PHYS + c * 64 + lane],      xv, a0);
                a1 = fmaf(sEnc[E_PHYS + c * 64 + lane + 32], xv, a1);
            }
            fr[lane] = fmaxf(a0, 0.f);
            fr[lane + 32] = fmaxf(a1, 0.f);
            // obj: 32 outputs over x[29:44]
            float a = sB[64 + lane];
            #pragma unroll
            for (int c = 0; c < 15; c++)
                a = fmaf(sEnc[E_OBJ + c * 32 + lane], xr[29 + c], a);
            fr[64 + lane] = fmaxf(a, 0.f);
            if (lane < 16) {
                float m = sB[96 + lane];
                #pragma unroll
                for (int c = 0; c < 8; c++)
                    m = fmaf(sEnc[E_MINE + c * 16 + lane], xr[44 + c], m);
                fr[96 + lane] = fmaxf(m, 0.f);
                float p = sB[112 + lane];
                #pragma unroll
                for (int c = 0; c < 3; c++)
                    p = fmaf(sEnc[E_PROG + c * 16 + lane], xr[52 + c], p);
                fr[112 + lane] = fmaxf(p, 0.f);
                float q = sB[128 + lane];
                #pragma unroll
                for (int c = 0; c < 3; c++)
                    q = fmaf(sEnc[E_SEQ + c * 16 + lane], xr[55 + c], q);
                fr[128 + lane] = fmaxf(q, 0.f);
            }
        }
        __syncthreads();

        // ---- phase 2: combined M-GEMM: Y[r][s][0:256] = tok|q|k|v ----
        {
            const int j = tid;
            float acc[RTILE];
            #pragma unroll
            for (int s = 0; s < 5; s++) {
                const float bias = g_Mb[s * 256 + j];
                #pragma unroll
                for (int r = 0; r < RTILE; r++) acc[r] = bias;
                switch (s) {
                    case 0: mgemm_seg<0,   64>(sM, sF, acc, j); break;
                    case 1: mgemm_seg<64,  32>(sM, sF, acc, j); break;
                    case 2: mgemm_seg<96,  16>(sM, sF, acc, j); break;
                    case 3: mgemm_seg<112, 16>(sM, sF, acc, j); break;
                    default: mgemm_seg<128, 16>(sM, sF, acc, j); break;
                }
                #pragma unroll
                for (int r = 0; r < RTILE; r++)
                    sY[r * 1280 + s * 256 + j] = acc[r];
            }
        }
        __syncthreads();

        // ---- phase 3: attention, warp = row, lanes 0..19 = (head, query) ----
        {
            const int r = w;
            float* Yr = sY + r * 1280;
            if (lane < 20) {
                const int h = lane / 5;
                const int i = lane - h * 5;
                const float* q = Yr + i * 256 + 64 + h * 16;
                float sc[5];
                #pragma unroll
                for (int jt = 0; jt < 5; jt++) {
                    const float* kk = Yr + jt * 256 + 128 + h * 16;
                    float d = 0.f;
                    #pragma unroll
                    for (int t = 0; t < 16; t++) d = fmaf(q[t], kk[t], d);
                    sc[jt] = d * 0.25f;
                }
                float mx = sc[0];
                #pragma unroll
                for (int jt = 1; jt < 5; jt++) mx = fmaxf(mx, sc[jt]);
                float sum = 0.f;
                #pragma unroll
                for (int jt = 0; jt < 5; jt++) { sc[jt] = __expf(sc[jt] - mx); sum += sc[jt]; }
                const float inv = 1.f / sum;
                #pragma unroll
                for (int t = 0; t < 16; t++) {
                    float c = 0.f;
                    #pragma unroll
                    for (int jt = 0; jt < 5; jt++)
                        c = fmaf(sc[jt], Yr[jt * 256 + 192 + h * 16 + t], c);
                    Yr[i * 256 + 64 + h * 16 + t] = c * inv;  // ctx -> q slot
                }
            }
        }
        __syncwarp();

        // ---- phase 4: Wo proj + residual + LN + pool, warp = row ----
        {
            const int r = w;
            const int j0 = lane * 2;
            const float* Yr = sY + r * 1280;
            float a0[5], a1[5];
            const float bo0 = sB[144 + j0], bo1 = sB[144 + j0 + 1];
            #pragma unroll
            for (int s = 0; s < 5; s++) { a0[s] = bo0; a1[s] = bo1; }
            for (int c = 0; c < 64; c++) {
                float2 w2 = *reinterpret_cast<const float2*>(g_WoT + c * 64 + j0);
                #pragma unroll
                for (int s = 0; s < 5; s++) {
                    float cv = Yr[s * 256 + 64 + c];   // ctx
                    a0[s] = fmaf(cv, w2.x, a0[s]);
                    a1[s] = fmaf(cv, w2.y, a1[s]);
                }
            }
            const float g0 = sB[208 + j0], g1 = sB[208 + j0 + 1];
            const float be0 = sB[272 + j0], be1 = sB[272 + j0 + 1];
            float p0 = 0.f, p1 = 0.f;
            #pragma unroll
            for (int s = 0; s < 5; s++) {
                float h0 = Yr[s * 256 + j0]     + a0[s];
                float h1 = Yr[s * 256 + j0 + 1] + a1[s];
                float sum = h0 + h1;
                #pragma unroll
                for (int o = 16; o > 0; o >>= 1)
                    sum += __shfl_xor_sync(0xffffffff, sum, o);
                const float mu = sum * (1.f / 64.f);
                const float d0 = h0 - mu, d1 = h1 - mu;
                float v = d0 * d0 + d1 * d1;
                #pragma unroll
                for (int o = 16; o > 0; o >>= 1)
                    v += __shfl_xor_sync(0xffffffff, v, o);
                const float invstd = rsqrtf(v * (1.f / 64.f) + 1e-5f);
                p0 = fmaf(d0 * invstd, g0, p0 + be0);
                p1 = fmaf(d1 * invstd, g1, p1 + be1);
            }
            sP[r * 64 + j0]     = p0 * 0.2f;
            sP[r * 64 + j0 + 1] = p1 * 0.2f;
        }
        __syncthreads();

        // ---- phase 5: head GEMM: out = relu(pooled @ Wp.T + bp) ----
        {
            const int o  = tid & 127;
            const int rh = tid >> 7;           // 0 or 1 -> rows rh*4 .. rh*4+3
            const float bb = bp[o];
            float a[4];
            #pragma unroll
            for (int k = 0; k < 4; k++) a[k] = bb;
            const float* pr = sP + rh * 4 * 64;
            #pragma unroll 4
            for (int c = 0; c < 64; c++) {
                float wv = g_WpT[c * 128 + o];
                #pragma unroll
                for (int k = 0; k < 4; k++)
                    a[k] = fmaf(pr[k * 64 + c], wv, a[k]);
            }
            #pragma unroll
            for (int k = 0; k < 4; k++)
                out[(size_t)(base + rh * 4 + k) * 128 + o] = fmaxf(a[k], 0.f);
        }
        __syncthreads();
    }
}

// ---------------------------------------------------------------------------
extern "C" void kernel_launch(void* const* d_in, const int* in_sizes, int n_in,
                              void* d_out, int out_size)
{
    const float* x       = (const float*)d_in[0];
    const float* W_phys  = (const float*)d_in[1];
    const float* b_phys  = (const float*)d_in[2];
    const float* W_obj   = (const float*)d_in[3];
    const float* b_obj   = (const float*)d_in[4];
    const float* W_mine  = (const float*)d_in[5];
    const float* b_mine  = (const float*)d_in[6];
    const float* W_prog  = (const float*)d_in[7];
    const float* b_prog  = (const float*)d_in[8];
    const float* W_seq   = (const float*)d_in[9];
    const float* b_seq   = (const float*)d_in[10];
    const float* P_phys  = (const float*)d_in[11];
    const float* pb_phys = (const float*)d_in[12];
    const float* P_obj   = (const float*)d_in[13];
    const float* pb_obj  = (const float*)d_in[14];
    const float* P_mine  = (const float*)d_in[15];
    const float* pb_mine = (const float*)d_in[16];
    const float* P_prog  = (const float*)d_in[17];
    const float* pb_prog = (const float*)d_in[18];
    const float* P_seq   = (const float*)d_in[19];
    const float* pb_seq  = (const float*)d_in[20];
    const float* Wqkv    = (const float*)d_in[21];
    const float* bqkv    = (const float*)d_in[22];
    const float* Wo      = (const float*)d_in[23];
    const float* bo      = (const float*)d_in[24];
    const float* gamma   = (const float*)d_in[25];
    const float* beta    = (const float*)d_in[26];
    const float* Wp      = (const float*)d_in[27];
    const float* bp      = (const float*)d_in[28];
    float* out = (float*)d_out;

    cudaFuncSetAttribute(fused_kernel,
                         cudaFuncAttributeMaxDynamicSharedMemorySize,
                         SMEM_BYTES);

    prep_kernel<<<207, 256>>>(Wqkv, bqkv,
                              P_phys, pb_phys, P_obj, pb_obj, P_mine, pb_mine,
                              P_prog, pb_prog, P_seq, pb_seq,
                              W_phys, W_obj, W_mine, W_prog, W_seq,
                              Wo, Wp);

    fused_kernel<<<GRID, NTHR, SMEM_BYTES>>>(
        x, b_phys, b_obj, b_mine, b_prog, b_seq,
        bo, gamma, beta, bp, out);
}

// round 8
// speedup vs baseline: 7.4049x; 1.2422x over previous
#include <cuda_runtime.h>

// ---------------------------------------------------------------------------
// AttentiveStateMLP — persistent block-tiled, 512-thread version.
// R7 ncu: fma 20%, issue 30.7%, occ 12.5% -> latency/barrier bound at 8 warps,
// with phase-4/5 weight loads going to global (L1D ~0 due to smem carveout).
// R8: 16 warps/SM, all hot weights in smem (Wo resident, Wp staged into dead
// sY region per tile), every phase spread across all 512 threads, padded sY
// strides (260/1304) for conflict-free attention accesses.
// ---------------------------------------------------------------------------

#define BATCH   131072
#define RTILE   8
#define NTILES  (BATCH / RTILE)     // 16384
#define NTHR    512

#define TS 260                       // token stride in sY (floats)
#define YS 1304                      // row stride in sY = 5*TS + 4

// smem layout (floats)
#define OFF_M    0                   // 36864 : combined M, k-major [c(144)][j(256)]
#define OFF_ENC  36864               // 2560  : encoder weights, k-major
#define OFF_WO   39424               // 4096  : WoT k-major [c(64)][j(64)]
#define OFF_MB   43520               // 1280  : per-token M bias
#define OFF_B    44800               // 464   : encbias144|bo64|gamma64|beta64|bp128
#define OFF_X    45264               // 512   : x tile 8 x 64
#define OFF_F    45776               // 1152  : features 8 x 144
#define OFF_Y    46928               // 10432 : 8 x YS  (tok|q/ctx|k/h|v) ; Wp staging
#define OFF_P    57360               // 512   : pooled 8 x 64
#define SMEM_FL  57872
#define SMEM_BYTES (SMEM_FL * 4)     // 231488 bytes (max dyn smem 232448)

// enc sub-offsets within OFF_ENC
#define E_PHYS 0       // 29 x 64
#define E_OBJ  1856    // 15 x 32
#define E_MINE 2336    // 8 x 16
#define E_PROG 2464    // 3 x 16
#define E_SEQ  2512    // 3 x 16

__device__ float g_M[144 * 256];   // k-major combined matrix [P_s ; Wqkv@P_s]
__device__ float g_Mb[5 * 256];    // per-token bias for M outputs
__device__ float g_encT[2560];     // k-major encoder weights
__device__ float g_WoT[64 * 64];   // WoT[c*64+j] = Wo[j][c]
__device__ float g_WpT[64 * 128];  // WpT[c*128+o] = Wp[o][c]

// ---------------------------------------------------------------------------
__global__ void prep_kernel(
    const float* __restrict__ Wqkv, const float* __restrict__ bqkv,
    const float* __restrict__ P_phys, const float* __restrict__ pb_phys,
    const float* __restrict__ P_obj,  const float* __restrict__ pb_obj,
    const float* __restrict__ P_mine, const float* __restrict__ pb_mine,
    const float* __restrict__ P_prog, const float* __restrict__ pb_prog,
    const float* __restrict__ P_seq,  const float* __restrict__ pb_seq,
    const float* __restrict__ W_phys, const float* __restrict__ W_obj,
    const float* __restrict__ W_mine, const float* __restrict__ W_prog,
    const float* __restrict__ W_seq,
    const float* __restrict__ Wo, const float* __restrict__ Wp)
{
    int idx = blockIdx.x * blockDim.x + threadIdx.x;

    if (idx < 36864) {                       // g_M[cg*256 + j]
        int cg = idx >> 8;
        int j  = idx & 255;
        const float* P; int dim, c;
        if (cg < 64)       { P = P_phys; dim = 64; c = cg; }
        else if (cg < 96)  { P = P_obj;  dim = 32; c = cg - 64; }
        else if (cg < 112) { P = P_mine; dim = 16; c = cg - 96; }
        else if (cg < 128) { P = P_prog; dim = 16; c = cg - 112; }
        else               { P = P_seq;  dim = 16; c = cg - 128; }
        float v;
        if (j < 64) {
            v = P[j * dim + c];
        } else {
            int jq = j - 64;
            float a = 0.f;
            for (int k = 0; k < 64; k++)
                a = fmaf(Wqkv[jq * 64 + k], P[k * dim + c], a);
            v = a;
        }
        g_M[idx] = v;
        return;
    }
    int i2 = idx - 36864;                    // g_Mb: 1280
    if (i2 < 1280) {
        int s = i2 >> 8;
        int j = i2 & 255;
        const float* pb = (s == 0) ? pb_phys : (s == 1) ? pb_obj :
                          (s == 2) ? pb_mine : (s == 3) ? pb_prog : pb_seq;
        float v;
        if (j < 64) {
            v = pb[j];
        } else {
            int jq = j - 64;
            float a = bqkv[jq];
            for (int k = 0; k < 64; k++)
                a = fmaf(Wqkv[jq * 64 + k], pb[k], a);
            v = a;
        }
        g_Mb[i2] = v;
        return;
    }
    int i3 = idx - 38144;                    // g_encT: 2560
    if (i3 < 2560) {
        float v;
        if (i3 < E_OBJ)        { int t = i3;          v = W_phys[(t & 63) * 29 + (t >> 6)]; }
        else if (i3 < E_MINE)  { int t = i3 - E_OBJ;  v = W_obj [(t & 31) * 15 + (t >> 5)]; }
        else if (i3 < E_PROG)  { int t = i3 - E_MINE; v = W_mine[(t & 15) *  8 + (t >> 4)]; }
        else if (i3 < E_SEQ)   { int t = i3 - E_PROG; v = W_prog[(t & 15) *  3 + (t >> 4)]; }
        else                   { int t = i3 - E_SEQ;  v = W_seq [(t & 15) *  3 + (t >> 4)]; }
        g_encT[i3] = v;
        return;
    }
    int i4 = idx - 40704;                    // g_WoT: 4096
    if (i4 < 4096) {
        int c = i4 >> 6, j = i4 & 63;
        g_WoT[i4] = Wo[j * 64 + c];
        return;
    }
    int i5 = idx - 44800;                    // g_WpT: 8192
    if (i5 < 8192) {
        int c = i5 >> 7, o = i5 & 127;
        g_WpT[i5] = Wp[o * 64 + c];
    }
}

// ---------------------------------------------------------------------------
template <int SOFF, int SDIM>
__device__ __forceinline__ void mgemm_seg4(const float* __restrict__ sM,
                                           const float* __restrict__ F0,
                                           float* acc, int j)
{
    const float* Ms = sM + SOFF * 256 + j;
    #pragma unroll
    for (int c = 0; c < SDIM; c += 4) {
        float w0 = Ms[(c + 0) * 256];
        float w1 = Ms[(c + 1) * 256];
        float w2 = Ms[(c + 2) * 256];
        float w3 = Ms[(c + 3) * 256];
        #pragma unroll
        for (int r = 0; r < 4; r++) {
            float4 f = *reinterpret_cast<const float4*>(F0 + r * 144 + SOFF + c);
            acc[r] = fmaf(f.x, w0, fmaf(f.y, w1, fmaf(f.z, w2, fmaf(f.w, w3, acc[r]))));
        }
    }
}

__global__ __launch_bounds__(NTHR, 1)
void fused_kernel(const float* __restrict__ x,
                  const float* __restrict__ b_phys, const float* __restrict__ b_obj,
                  const float* __restrict__ b_mine, const float* __restrict__ b_prog,
                  const float* __restrict__ b_seq,
                  const float* __restrict__ bo, const float* __restrict__ gamma,
                  const float* __restrict__ beta, const float* __restrict__ bp,
                  float* __restrict__ out)
{
    extern __shared__ float sm[];
    float* sM   = sm + OFF_M;
    float* sEnc = sm + OFF_ENC;
    float* sWo  = sm + OFF_WO;
    float* sMb  = sm + OFF_MB;
    float* sB   = sm + OFF_B;
    float* sX   = sm + OFF_X;
    float* sF   = sm + OFF_F;
    float* sY   = sm + OFF_Y;
    float* sP   = sm + OFF_P;

    const int tid = threadIdx.x;

    // ---- preload all weights into smem once per block ----
    for (int i = tid; i < 36864; i += NTHR) sM[i]   = g_M[i];
    for (int i = tid; i < 2560;  i += NTHR) sEnc[i] = g_encT[i];
    for (int i = tid; i < 4096;  i += NTHR) sWo[i]  = g_WoT[i];
    for (int i = tid; i < 1280;  i += NTHR) sMb[i]  = g_Mb[i];
    for (int i = tid; i < 464; i += NTHR) {
        float v;
        if (i < 64)       v = b_phys[i];
        else if (i < 96)  v = b_obj[i - 64];
        else if (i < 112) v = b_mine[i - 96];
        else if (i < 128) v = b_prog[i - 112];
        else if (i < 144) v = b_seq[i - 128];
        else if (i < 208) v = bo[i - 144];
        else if (i < 272) v = gamma[i - 208];
        else if (i < 336) v = beta[i - 272];
        else              v = bp[i - 336];
        sB[i] = v;
    }
    __syncthreads();

    for (int tile = blockIdx.x; tile < NTILES; tile += gridDim.x) {
        const int base = tile * RTILE;

        // ---- P0: load x tile (coalesced) ----
        if (tid < RTILE * 58) {
            int r = tid / 58, c = tid - r * 58;
            sX[r * 64 + c] = x[(size_t)base * 58 + tid];
        }
        __syncthreads();

        // ---- P1: encoders, thread-per-output ----
        {
            int r = tid >> 6, j = tid & 63;          // phys: 8 x 64 = 512
            const float* xr = sX + r * 64;
            float a = sB[j];
            #pragma unroll
            for (int c = 0; c < 29; c++)
                a = fmaf(sEnc[E_PHYS + c * 64 + j], xr[c], a);
            sF[r * 144 + j] = fmaxf(a, 0.f);
        }
        if (tid < 256) {                              // obj: 8 x 32
            int r = tid >> 5, j = tid & 31;
            const float* xr = sX + r * 64;
            float a = sB[64 + j];
            #pragma unroll
            for (int c = 0; c < 15; c++)
                a = fmaf(sEnc[E_OBJ + c * 32 + j], xr[29 + c], a);
            sF[r * 144 + 64 + j] = fmaxf(a, 0.f);
        }
        if (tid < 384) {                              // mine/prog/seq: 3 x 8 x 16
            int seg = tid >> 7;
            int t = tid & 127;
            int r = t >> 4, j = t & 15;
            const float* xr = sX + r * 64;
            const float* W; int xo, kk, oo;
            float a;
            if (seg == 0)      { W = sEnc + E_MINE; xo = 44; kk = 8; oo = 96;  a = sB[96 + j]; }
            else if (seg == 1) { W = sEnc + E_PROG; xo = 52; kk = 3; oo = 112; a = sB[112 + j]; }
            else               { W = sEnc + E_SEQ;  xo = 55; kk = 3; oo = 128; a = sB[128 + j]; }
            for (int c = 0; c < kk; c++)
                a = fmaf(W[c * 16 + j], xr[xo + c], a);
            sF[r * 144 + oo + j] = fmaxf(a, 0.f);
        }
        __syncthreads();

        // ---- P2: M-GEMM  Y[r][s][0:256] = tok|q|k|v ----
        {
            const int j  = tid & 255;
            const int g  = tid >> 8;        // 0,1 -> rows 4g..4g+3
            const float* F0 = sF + (g * 4) * 144;
            float* Y0 = sY + (g * 4) * YS;
            float acc[4];
            #pragma unroll
            for (int s = 0; s < 5; s++) {
                const float bias = sMb[s * 256 + j];
                #pragma unroll
                for (int r = 0; r < 4; r++) acc[r] = bias;
                switch (s) {
                    case 0:  mgemm_seg4<0,   64>(sM, F0, acc, j); break;
                    case 1:  mgemm_seg4<64,  32>(sM, F0, acc, j); break;
                    case 2:  mgemm_seg4<96,  16>(sM, F0, acc, j); break;
                    case 3:  mgemm_seg4<112, 16>(sM, F0, acc, j); break;
                    default: mgemm_seg4<128, 16>(sM, F0, acc, j); break;
                }
                // scatter j (0..255) into padded token slots: slot = j>>6, off = j&63
                const int slot = j >> 6, joff = j & 63;
                #pragma unroll
                for (int r = 0; r < 4; r++)
                    Y0[r * YS + s * TS + slot * 64 + joff] = acc[r];
            }
        }
        __syncthreads();

        // ---- P3: attention (160 units: row x head x query) ----
        if (tid < 160) {
            const int r  = tid & 7;
            const int hi = tid >> 3;
            const int h  = hi / 5;
            const int i  = hi - h * 5;
            float* Yr = sY + r * YS;
            const float4* q4 = reinterpret_cast<const float4*>(Yr + i * TS + 64 + h * 16);
            const float4 q0 = q4[0], q1 = q4[1], q2 = q4[2], q3 = q4[3];
            float sc[5];
            #pragma unroll
            for (int jt = 0; jt < 5; jt++) {
                const float4* k4 = reinterpret_cast<const float4*>(Yr + jt * TS + 128 + h * 16);
                float4 k0 = k4[0], k1 = k4[1], k2 = k4[2], k3 = k4[3];
                float d = q0.x * k0.x + q0.y * k0.y + q0.z * k0.z + q0.w * k0.w;
                d = fmaf(q1.x, k1.x, fmaf(q1.y, k1.y, fmaf(q1.z, k1.z, fmaf(q1.w, k1.w, d))));
                d = fmaf(q2.x, k2.x, fmaf(q2.y, k2.y, fmaf(q2.z, k2.z, fmaf(q2.w, k2.w, d))));
                d = fmaf(q3.x, k3.x, fmaf(q3.y, k3.y, fmaf(q3.z, k3.z, fmaf(q3.w, k3.w, d))));
                sc[jt] = d * 0.25f;
            }
            float mx = sc[0];
            #pragma unroll
            for (int jt = 1; jt < 5; jt++) mx = fmaxf(mx, sc[jt]);
            float sum = 0.f;
            #pragma unroll
            for (int jt = 0; jt < 5; jt++) { sc[jt] = __expf(sc[jt] - mx); sum += sc[jt]; }
            const float inv = 1.f / sum;
            #pragma unroll
            for (int tq = 0; tq < 4; tq++) {
                float4 c = make_float4(0.f, 0.f, 0.f, 0.f);
                #pragma unroll
                for (int jt = 0; jt < 5; jt++) {
                    const float4 v = reinterpret_cast<const float4*>(
                        Yr + jt * TS + 192 + h * 16)[tq];
                    c.x = fmaf(sc[jt], v.x, c.x);
                    c.y = fmaf(sc[jt], v.y, c.y);
                    c.z = fmaf(sc[jt], v.z, c.z);
                    c.w = fmaf(sc[jt], v.w, c.w);
                }
                c.x *= inv; c.y *= inv; c.z *= inv; c.w *= inv;
                reinterpret_cast<float4*>(Yr + i * TS + 64 + h * 16)[tq] = c;  // ctx->q slot
            }
        }
        __syncthreads();

        // ---- P4a: Wo projection + residual -> h (into k slot) ----
        {
            const int j = tid & 63;
            const int u = tid >> 6;          // row
            float* Yr = sY + u * YS;
            const float bov = sB[144 + j];
            float acc[5];
            #pragma unroll
            for (int s = 0; s < 5; s++) acc[s] = bov;
            #pragma unroll 4
            for (int c = 0; c < 64; c += 4) {
                float w0 = sWo[(c + 0) * 64 + j];
                float w1 = sWo[(c + 1) * 64 + j];
                float w2 = sWo[(c + 2) * 64 + j];
                float w3 = sWo[(c + 3) * 64 + j];
                #pragma unroll
                for (int s = 0; s < 5; s++) {
                    const float4 cv = *reinterpret_cast<const float4*>(Yr + s * TS + 64 + c);
                    acc[s] = fmaf(cv.x, w0, fmaf(cv.y, w1, fmaf(cv.z, w2, fmaf(cv.w, w3, acc[s]))));
                }
            }
            #pragma unroll
            for (int s = 0; s < 5; s++)
                Yr[s * TS + 128 + j] = Yr[s * TS + j] + acc[s];   // h = tok + proj
        }
        __syncthreads();

        // ---- P4b: LayerNorm + pool (warp per row) ----
        if (tid < 256) {
            const int r = tid >> 5, lane = tid & 31;
            const int j0 = lane * 2;
            float* Yr = sY + r * YS;
            const float g0 = sB[208 + j0], g1 = sB[208 + j0 + 1];
            const float be0 = sB[272 + j0], be1 = sB[272 + j0 + 1];
            float p0 = 0.f, p1 = 0.f;
            #pragma unroll
            for (int s = 0; s < 5; s++) {
                const float2 h2 = *reinterpret_cast<const float2*>(Yr + s * TS + 128 + j0);
                float sum = h2.x + h2.y;
                #pragma unroll
                for (int o = 16; o > 0; o >>= 1)
                    sum += __shfl_xor_sync(0xffffffff, sum, o);
                const float mu = sum * (1.f / 64.f);
                const float d0 = h2.x - mu, d1 = h2.y - mu;
                float v = d0 * d0 + d1 * d1;
                #pragma unroll
                for (int o = 16; o > 0; o >>= 1)
                    v += __shfl_xor_sync(0xffffffff, v, o);
                const float invstd = rsqrtf(v * (1.f / 64.f) + 1e-5f);
                p0 = fmaf(d0 * invstd, g0, p0 + be0);
                p1 = fmaf(d1 * invstd, g1, p1 + be1);
            }
            sP[r * 64 + j0]     = p0 * 0.2f;
            sP[r * 64 + j0 + 1] = p1 * 0.2f;
        }
        __syncthreads();

        // ---- P5: stage Wp into (dead) sY, then head GEMM ----
        {
            float4* dst = reinterpret_cast<float4*>(sY);
            const float4* src = reinterpret_cast<const float4*>(g_WpT);
            #pragma unroll
            for (int q = 0; q < 4; q++) dst[tid + q * NTHR] = src[tid + q * NTHR];
        }
        __syncthreads();
        {
            const int o  = tid & 127;
            const int r0 = (tid >> 7) * 2;           // rows r0, r0+1
            const float* sWp = sY;
            float a0 = sB[336 + o], a1 = a0;
            #pragma unroll 4
            for (int c = 0; c < 64; c += 4) {
                float w0 = sWp[(c + 0) * 128 + o];
                float w1 = sWp[(c + 1) * 128 + o];
                float w2 = sWp[(c + 2) * 128 + o];
                float w3 = sWp[(c + 3) * 128 + o];
                const float4 f0 = *reinterpret_cast<const float4*>(sP + r0 * 64 + c);
                const float4 f1 = *reinterpret_cast<const float4*>(sP + (r0 + 1) * 64 + c);
                a0 = fmaf(f0.x, w0, fmaf(f0.y, w1, fmaf(f0.z, w2, fmaf(f0.w, w3, a0))));
                a1 = fmaf(f1.x, w0, fmaf(f1.y, w1, fmaf(f1.z, w2, fmaf(f1.w, w3, a1))));
            }
            out[(size_t)(base + r0) * 128 + o]     = fmaxf(a0, 0.f);
            out[(size_t)(base + r0 + 1) * 128 + o] = fmaxf(a1, 0.f);
        }
        __syncthreads();
    }
}

// ---------------------------------------------------------------------------
extern "C" void kernel_launch(void* const* d_in, const int* in_sizes, int n_in,
                              void* d_out, int out_size)
{
    const float* x       = (const float*)d_in[0];
    const float* W_phys  = (const float*)d_in[1];
    const float* b_phys  = (const float*)d_in[2];
    const float* W_obj   = (const float*)d_in[3];
    const float* b_obj   = (const float*)d_in[4];
    const float* W_mine  = (const float*)d_in[5];
    const float* b_mine  = (const float*)d_in[6];
    const float* W_prog  = (const float*)d_in[7];
    const float* b_prog  = (const float*)d_in[8];
    const float* W_seq   = (const float*)d_in[9];
    const float* b_seq   = (const float*)d_in[10];
    const float* P_phys  = (const float*)d_in[11];
    const float* pb_phys = (const float*)d_in[12];
    const float* P_obj   = (const float*)d_in[13];
    const float* pb_obj  = (const float*)d_in[14];
    const float* P_mine  = (const float*)d_in[15];
    const float* pb_mine = (const float*)d_in[16];
    const float* P_prog  = (const float*)d_in[17];
    const float* pb_prog = (const float*)d_in[18];
    const float* P_seq   = (const float*)d_in[19];
    const float* pb_seq  = (const float*)d_in[20];
    const float* Wqkv    = (const float*)d_in[21];
    const float* bqkv    = (const float*)d_in[22];
    const float* Wo      = (const float*)d_in[23];
    const float* bo      = (const float*)d_in[24];
    const float* gamma   = (const float*)d_in[25];
    const float* beta    = (const float*)d_in[26];
    const float* Wp      = (const float*)d_in[27];
    const float* bp      = (const float*)d_in[28];
    float* out = (float*)d_out;

    cudaFuncSetAttribute(fused_kernel,
                         cudaFuncAttributeMaxDynamicSharedMemorySize,
                         SMEM_BYTES);

    int dev = 0, sms = 148;
    cudaGetDevice(&dev);
    cudaDeviceGetAttribute(&sms, cudaDevAttrMultiProcessorCount, dev);

    prep_kernel<<<207, 256>>>(Wqkv, bqkv,
                              P_phys, pb_phys, P_obj, pb_obj, P_mine, pb_mine,
                              P_prog, pb_prog, P_seq, pb_seq,
                              W_phys, W_obj, W_mine, W_prog, W_seq,
                              Wo, Wp);

    fused_kernel<<<sms, NTHR, SMEM_BYTES>>>(
        x, b_phys, b_obj, b_mine, b_prog, b_seq,
        bo, gamma, beta, bp, out);
}